// round 7
// baseline (speedup 1.0000x reference)
#include <cuda_runtime.h>

#define BB 8
#define LL 512
#define DD 128
#define INV_SCALE 0.08838834764831843f   // 1/sqrt(128)

typedef unsigned long long ull;

// ---- scratch (no cudaMalloc allowed) ----
__device__ float g_TQ[BB*LL*DD];   // tanh(Q proj)
__device__ float g_TK[BB*LL*DD];   // tanh(K proj)
__device__ float g_V [BB*LL*DD];

__device__ __forceinline__ float fast_tanh(float x) {
    float y;
    asm("tanh.approx.f32 %0, %1;" : "=f"(y) : "f"(x));
    return y;
}
__device__ __forceinline__ float frcp(float x) {
    float y;
    asm("rcp.approx.f32 %0, %1;" : "=f"(y) : "f"(x));
    return y;
}
__device__ __forceinline__ ull ffma2(ull a, ull b, ull c) {
    ull d;
    asm("fma.rn.f32x2 %0, %1, %2, %3;" : "=l"(d) : "l"(a), "l"(b), "l"(c));
    return d;
}
__device__ __forceinline__ ull fmul2(ull a, ull b) {
    ull d;
    asm("mul.rn.f32x2 %0, %1, %2;" : "=l"(d) : "l"(a), "l"(b));
    return d;
}
__device__ __forceinline__ ull pack2(float x) {
    ull d;
    asm("mov.b64 %0, {%1, %1};" : "=l"(d) : "f"(x));
    return d;
}
__device__ __forceinline__ ull pack2two(float x, float y) {
    ull d;
    asm("mov.b64 %0, {%1, %2};" : "=l"(d) : "f"(x), "f"(y));
    return d;
}
__device__ __forceinline__ float2 unpack2(ull v) {
    float2 r;
    asm("mov.b64 {%0, %1}, %2;" : "=f"(r.x), "=f"(r.y) : "l"(v));
    return r;
}

// =====================================================================
// Projection: out = tanh?(X @ W.T + b)   (FFMA2, packed col pairs)
// grid 96 (mat = bx>>5, 128-row tile = bx&31), 256 threads (R3 config)
// Q,K paths write tanh(proj); V path writes proj.
// =====================================================================
#define XS_PITCH 129
#define WT_PITCH 130
#define PROJ_SMEM_FLOATS (128*XS_PITCH + 128*WT_PITCH)

__global__ void __launch_bounds__(256) proj_kernel(
    const float* __restrict__ Xq, const float* __restrict__ Xk, const float* __restrict__ Xv,
    const float* __restrict__ Wq, const float* __restrict__ bq,
    const float* __restrict__ Wk, const float* __restrict__ bk,
    const float* __restrict__ Wv, const float* __restrict__ bv)
{
    extern __shared__ float sm[];
    float* Xs = sm;                    // [128][129]
    float* Wt = sm + 128*XS_PITCH;     // [128][130]  Wt[d][c]
    __shared__ float bs[DD];

    int bx  = blockIdx.x;
    int mat = bx >> 5;
    int rt  = bx & 31;
    const float *X, *W, *bias;
    float* out;
    if (mat == 0)      { X = Xq; W = Wq; bias = bq; out = g_TQ; }
    else if (mat == 1) { X = Xk; W = Wk; bias = bk; out = g_TK; }
    else               { X = Xv; W = Wv; bias = bv; out = g_V;  }

    int tid = threadIdx.x;
    const float4* Xg = (const float4*)(X + rt*128*DD);
    const float4* Wg = (const float4*)W;
    #pragma unroll
    for (int it = 0; it < 16; ++it) {
        int idx = it*256 + tid;           // 0..4095 float4 groups
        int d4  = idx & 31;               // d = 4*d4
        int r   = idx >> 5;               // row (or out-col c for W)
        float4 xv = Xg[idx];
        float* xd = Xs + r*XS_PITCH + 4*d4;
        xd[0] = xv.x; xd[1] = xv.y; xd[2] = xv.z; xd[3] = xv.w;
        float4 wv = Wg[idx];
        Wt[(4*d4+0)*WT_PITCH + r] = wv.x;
        Wt[(4*d4+1)*WT_PITCH + r] = wv.y;
        Wt[(4*d4+2)*WT_PITCH + r] = wv.z;
        Wt[(4*d4+3)*WT_PITCH + r] = wv.w;
    }
    if (tid < DD) bs[tid] = bias[tid];
    __syncthreads();

    int tr = tid >> 4;     // 0..15 (8-row group)
    int tc = tid & 15;     // 0..15 (8-col group)
    const float* xb = Xs + (tr*8)*XS_PITCH;
    const float* wb = Wt + tc*8;

    ull acc[8][4];
    #pragma unroll
    for (int i = 0; i < 8; ++i)
        #pragma unroll
        for (int j = 0; j < 4; ++j) acc[i][j] = 0ull;

    #pragma unroll 4
    for (int d = 0; d < DD; ++d) {
        float xs[8]; ull xp[8]; ull wp[4];
        #pragma unroll
        for (int i = 0; i < 8; ++i) xs[i] = xb[i*XS_PITCH + d];
        #pragma unroll
        for (int j = 0; j < 4; ++j) wp[j] = *(const ull*)(wb + d*WT_PITCH + 2*j);
        #pragma unroll
        for (int i = 0; i < 8; ++i) xp[i] = pack2(xs[i]);
        #pragma unroll
        for (int i = 0; i < 8; ++i)
            #pragma unroll
            for (int j = 0; j < 4; ++j) acc[i][j] = ffma2(xp[i], wp[j], acc[i][j]);
    }

    int rbase = rt*128 + tr*8;
    #pragma unroll
    for (int i = 0; i < 8; ++i) {
        float* orow = out + (rbase + i)*DD + tc*8;
        #pragma unroll
        for (int j = 0; j < 4; ++j) {
            float2 v = unpack2(acc[i][j]);
            float o0 = v.x + bs[tc*8 + 2*j+0];
            float o1 = v.y + bs[tc*8 + 2*j+1];
            if (mat != 2) { o0 = fast_tanh(o0); o1 = fast_tanh(o1); }
            orow[2*j+0] = o0;
            orow[2*j+1] = o1;
        }
    }
}

// =====================================================================
// Attention. Per block: one batch b, one 32-row q tile. 1024 threads.
// Phase 1: score = sum_d w_d*(tq+tk)/(1+tq*tk), d-paired so ONE MUFU.RCP
//          serves 2 elements; all other math fma.rn.f32x2 over k-col pairs.
// Phase 2: warp-per-row softmax (b_all softmax-invariant -> dropped)
// Phase 3: O = P @ V with fma.rn.f32x2 (V packed in k-adjacent pairs)
// smem (floats):
//   S[32][512]                    @ 0       (16384)
//   TKs[128][66] / Vp[32][128]ull @ 16384   (8448 used; Vp needs 8192)
//   RT[32][64] float4 (tq0,wtq0,tq1,wtq1)  @ 24832 (8192)
//   WT[64] ull2 ((w0,w0),(w1,w1))          @ 33024 (256)
//   wall[128]                              @ 33280
//   rinv[32]                               @ 33408
// =====================================================================
#define SM_S    0
#define SM_TKS  (32*512)            // byte 65536: 8B/16B aligned
#define SM_RT   (SM_TKS + 8448)     // byte 99328: 16B aligned
#define SM_WT   (SM_RT + 32*64*4)   // byte 132096: 16B aligned
#define SM_WALL (SM_WT + 256)
#define SM_RINV (SM_WALL + 128)
#define ATTN_SMEM_FLOATS (SM_RINV + 32)   // 33440 floats = 133760 B

__global__ void __launch_bounds__(1024) attn_kernel(
    const float* __restrict__ wdel, const float* __restrict__ wsig,
    const float* __restrict__ wthe, float* __restrict__ out)
{
    extern __shared__ float sm[];
    float*      S    = sm + SM_S;
    float*      TKsF = sm + SM_TKS;
    ull*        TKs  = (ull*)TKsF;              // [128][33] col pairs (k, k+32)
    float4*     RT   = (float4*)(sm + SM_RT);   // [32][64]
    ulonglong2* WT   = (ulonglong2*)(sm + SM_WT); // [64]
    float*      wall = sm + SM_WALL;
    float*      rinv = sm + SM_RINV;

    int tid  = threadIdx.x;
    int w    = tid >> 5;
    int lane = tid & 31;
    int b    = blockIdx.x >> 4;
    int qt   = blockIdx.x & 15;
    int qbase = qt * 32;

    const float* TQg = g_TQ + (b*LL + qbase)*DD;
    const float* TKg = g_TK + b*LL*DD;
    const float* Vg  = g_V  + b*LL*DD;

    if (tid < DD) wall[tid] = INV_SCALE + wdel[tid] + wsig[tid] + wthe[tid];
    __syncthreads();

    // Row table RT[r][d2] = (tq_d0, w_d0*tq_d0, tq_d1, w_d1*tq_d1)
    #pragma unroll
    for (int it = 0; it < 2; ++it) {
        int e  = it*1024 + tid;            // 0..2047
        int r  = e >> 6, d2 = e & 63;
        float2 t2 = *(const float2*)(TQg + r*DD + 2*d2);
        RT[r*64 + d2] = make_float4(t2.x, wall[2*d2]*t2.x,
                                    t2.y, wall[2*d2+1]*t2.y);
    }
    if (tid < 64) {
        ulonglong2 u;
        u.x = pack2(wall[2*tid]);
        u.y = pack2(wall[2*tid+1]);
        WT[tid] = u;
    }
    // (first loop __syncthreads orders RT/WT for all warps)

    // ---------------- Phase 1: scores ----------------
    const float4* RTrow = RT + w*64;
    const ull ONE2 = pack2(1.0f);
    for (int kt = 0; kt < 8; ++kt) {
        __syncthreads();   // TKs region free
        // stage TKs[d][2*col+half] = tanhK[kt*64 + half*32 + col][d]
        {
            const float4* TK4 = (const float4*)(TKg + kt*64*DD);
            int d4  = tid >> 5;        // 0..31
            int col = lane;            // 0..31
            #pragma unroll
            for (int half = 0; half < 2; ++half) {
                int k = half*32 + col;
                float4 v = TK4[k*32 + d4];
                TKsF[(4*d4+0)*66 + 2*col + half] = v.x;
                TKsF[(4*d4+1)*66 + 2*col + half] = v.y;
                TKsF[(4*d4+2)*66 + 2*col + half] = v.z;
                TKsF[(4*d4+3)*66 + 2*col + half] = v.w;
            }
        }
        __syncthreads();

        ull acc = 0ull;   // (0.0f, 0.0f)
        #pragma unroll 4
        for (int d2 = 0; d2 < 64; ++d2) {
            ull K0 = TKs[(2*d2)*33 + lane];      // (tk[k], tk[k+32]) at d0
            ull K1 = TKs[(2*d2+1)*33 + lane];    // at d1
            float4 rt = RTrow[d2];
            ulonglong2 wt = WT[d2];
            ull tq0  = pack2(rt.x), wtq0 = pack2(rt.y);
            ull tq1  = pack2(rt.z), wtq1 = pack2(rt.w);
            ull e0  = ffma2(tq0, K0, ONE2);            // 1 + tq*tk
            ull e1  = ffma2(tq1, K1, ONE2);
            ull wn0 = ffma2(wt.x, K0, wtq0);           // w*(tq+tk)
            ull wn1 = ffma2(wt.y, K1, wtq1);
            ull num = ffma2(wn1, e0, fmul2(wn0, e1));  // wn0*e1 + wn1*e0
            ull Dp  = fmul2(e0, e1);
            float2 Df = unpack2(Dp);
            ull R = pack2two(frcp(Df.x), frcp(Df.y));
            acc = ffma2(num, R, acc);
        }
        float2 a = unpack2(acc);
        S[w*512 + kt*64 + lane]      = a.x;
        S[w*512 + kt*64 + 32 + lane] = a.y;
    }
    // each warp softmaxes the row it wrote itself -> no sync needed here

    // ---------------- Phase 2: softmax ----------------
    {
        float* Srow = S + w*512;
        float v[16];
        float m = -1e30f;
        #pragma unroll
        for (int i = 0; i < 16; ++i) { v[i] = Srow[i*32 + lane]; m = fmaxf(m, v[i]); }
        #pragma unroll
        for (int s = 16; s > 0; s >>= 1) m = fmaxf(m, __shfl_xor_sync(0xffffffffu, m, s));
        float sum = 0.f;
        #pragma unroll
        for (int i = 0; i < 16; ++i) {
            float e = __expf(v[i] - m);
            Srow[i*32 + lane] = e;
            sum += e;
        }
        #pragma unroll
        for (int s = 16; s > 0; s >>= 1) sum += __shfl_xor_sync(0xffffffffu, sum, s);
        if (lane == 0) rinv[w] = 1.0f / sum;
    }

    // ---------------- Phase 3: O = P @ V (FFMA2) ----------------
    // warp -> 2 rows (w&15), 64-col half (w>>4); lane owns d = dA and dA+32
    int r0  = (w & 15) * 2;
    int dh  = w >> 4;
    int dA  = dh*64 + lane;
    ull acc3[2][2] = {{0,0},{0,0}};
    const ull* Vp = (const ull*)(sm + SM_TKS);   // [32][128] : Vp[k2][d]

    for (int kt = 0; kt < 8; ++kt) {
        __syncthreads();   // previous tile consumed / TKs done
        {
            const float4* Va = (const float4*)(Vg + kt*64*DD);
            float2* Vp2 = (float2*)(sm + SM_TKS);
            int k2 = tid >> 5, d4 = tid & 31;    // 1024 threads cover 32x32
            float4 a  = Va[(2*k2)*32 + d4];
            float4 bb = Va[(2*k2+1)*32 + d4];
            Vp2[k2*128 + 4*d4 + 0] = make_float2(a.x, bb.x);
            Vp2[k2*128 + 4*d4 + 1] = make_float2(a.y, bb.y);
            Vp2[k2*128 + 4*d4 + 2] = make_float2(a.z, bb.z);
            Vp2[k2*128 + 4*d4 + 3] = make_float2(a.w, bb.w);
        }
        __syncthreads();

        const float* Sb = S + kt*64;
        #pragma unroll 4
        for (int k2 = 0; k2 < 32; ++k2) {
            ull p0 = *(const ull*)(Sb + (r0+0)*512 + 2*k2);
            ull p1 = *(const ull*)(Sb + (r0+1)*512 + 2*k2);
            ull v0 = Vp[k2*128 + dA];
            ull v1 = Vp[k2*128 + dA + 32];
            acc3[0][0] = ffma2(p0, v0, acc3[0][0]);  acc3[0][1] = ffma2(p0, v1, acc3[0][1]);
            acc3[1][0] = ffma2(p1, v0, acc3[1][0]);  acc3[1][1] = ffma2(p1, v1, acc3[1][1]);
        }
    }

    #pragma unroll
    for (int i = 0; i < 2; ++i) {
        float inv = rinv[r0 + i];
        float2 eo = unpack2(acc3[i][0]);
        float2 e1 = unpack2(acc3[i][1]);
        float* orow = out + (size_t)(b*LL + qbase + r0 + i)*DD;
        orow[dA]      = (eo.x + eo.y) * inv;
        orow[dA + 32] = (e1.x + e1.y) * inv;
    }
}

// =====================================================================
extern "C" void kernel_launch(void* const* d_in, const int* in_sizes, int n_in,
                              void* d_out, int out_size)
{
    const float* query = (const float*)d_in[0];
    const float* key   = (const float*)d_in[1];
    const float* value = (const float*)d_in[2];
    const float* Wq    = (const float*)d_in[3];
    const float* bq    = (const float*)d_in[4];
    const float* Wk    = (const float*)d_in[5];
    const float* bk    = (const float*)d_in[6];
    const float* Wv    = (const float*)d_in[7];
    const float* bv    = (const float*)d_in[8];
    const float* wdel  = (const float*)d_in[9];
    const float* wsig  = (const float*)d_in[11];
    const float* wthe  = (const float*)d_in[13];
    float* out = (float*)d_out;

    const int PROJ_SMEM = PROJ_SMEM_FLOATS * (int)sizeof(float);
    const int ATTN_SMEM = ATTN_SMEM_FLOATS * (int)sizeof(float);

    cudaFuncSetAttribute(proj_kernel, cudaFuncAttributeMaxDynamicSharedMemorySize, PROJ_SMEM);
    cudaFuncSetAttribute(attn_kernel, cudaFuncAttributeMaxDynamicSharedMemorySize, ATTN_SMEM);

    proj_kernel<<<96, 256, PROJ_SMEM>>>(query, key, value, Wq, bq, Wk, bk, Wv, bv);
    attn_kernel<<<BB*16, 1024, ATTN_SMEM>>>(wdel, wsig, wthe, out);
}

// round 8
// speedup vs baseline: 1.0270x; 1.0270x over previous
#include <cuda_runtime.h>

#define BB 8
#define LL 512
#define DD 128
#define INV_SCALE 0.08838834764831843f   // 1/sqrt(128)

typedef unsigned long long ull;

// ---- scratch (no cudaMalloc allowed) ----
__device__ float g_EQ[BB*LL*DD];   // exp(2*Qproj)
__device__ float g_EK[BB*LL*DD];   // exp(2*Kproj)
__device__ float g_V [BB*LL*DD];

__device__ __forceinline__ float frcp(float x) {
    float y;
    asm("rcp.approx.f32 %0, %1;" : "=f"(y) : "f"(x));
    return y;
}
__device__ __forceinline__ ull ffma2(ull a, ull b, ull c) {
    ull d;
    asm("fma.rn.f32x2 %0, %1, %2, %3;" : "=l"(d) : "l"(a), "l"(b), "l"(c));
    return d;
}
__device__ __forceinline__ ull fmul2(ull a, ull b) {
    ull d;
    asm("mul.rn.f32x2 %0, %1, %2;" : "=l"(d) : "l"(a), "l"(b));
    return d;
}
__device__ __forceinline__ ull pack2(float x) {
    ull d;
    asm("mov.b64 %0, {%1, %1};" : "=l"(d) : "f"(x));
    return d;
}
__device__ __forceinline__ ull pack2two(float x, float y) {
    ull d;
    asm("mov.b64 %0, {%1, %2};" : "=l"(d) : "f"(x), "f"(y));
    return d;
}
__device__ __forceinline__ float2 unpack2(ull v) {
    float2 r;
    asm("mov.b64 {%0, %1}, %2;" : "=f"(r.x), "=f"(r.y) : "l"(v));
    return r;
}

// =====================================================================
// Projection: FFMA2 GEMM; epilogue writes exp(2*(XW^T+b)) for Q,K and
// raw proj for V.  grid 96, 256 threads.
// =====================================================================
#define XS_PITCH 129
#define WT_PITCH 130
#define PROJ_SMEM_FLOATS (128*XS_PITCH + 128*WT_PITCH)

__global__ void __launch_bounds__(256) proj_kernel(
    const float* __restrict__ Xq, const float* __restrict__ Xk, const float* __restrict__ Xv,
    const float* __restrict__ Wq, const float* __restrict__ bq,
    const float* __restrict__ Wk, const float* __restrict__ bk,
    const float* __restrict__ Wv, const float* __restrict__ bv)
{
    extern __shared__ float sm[];
    float* Xs = sm;                    // [128][129]
    float* Wt = sm + 128*XS_PITCH;     // [128][130]  Wt[d][c]
    __shared__ float bs[DD];

    int bx  = blockIdx.x;
    int mat = bx >> 5;
    int rt  = bx & 31;
    const float *X, *W, *bias;
    float* out;
    if (mat == 0)      { X = Xq; W = Wq; bias = bq; out = g_EQ; }
    else if (mat == 1) { X = Xk; W = Wk; bias = bk; out = g_EK; }
    else               { X = Xv; W = Wv; bias = bv; out = g_V;  }

    int tid = threadIdx.x;
    const float4* Xg = (const float4*)(X + rt*128*DD);
    const float4* Wg = (const float4*)W;
    #pragma unroll
    for (int it = 0; it < 16; ++it) {
        int idx = it*256 + tid;           // 0..4095 float4 groups
        int d4  = idx & 31;
        int r   = idx >> 5;
        float4 xv = Xg[idx];
        float* xd = Xs + r*XS_PITCH + 4*d4;
        xd[0] = xv.x; xd[1] = xv.y; xd[2] = xv.z; xd[3] = xv.w;
        float4 wv = Wg[idx];
        Wt[(4*d4+0)*WT_PITCH + r] = wv.x;
        Wt[(4*d4+1)*WT_PITCH + r] = wv.y;
        Wt[(4*d4+2)*WT_PITCH + r] = wv.z;
        Wt[(4*d4+3)*WT_PITCH + r] = wv.w;
    }
    if (tid < DD) bs[tid] = bias[tid];
    __syncthreads();

    int tr = tid >> 4;     // 0..15 (8-row group)
    int tc = tid & 15;     // 0..15 (8-col group)
    const float* xb = Xs + (tr*8)*XS_PITCH;
    const float* wb = Wt + tc*8;

    ull acc[8][4];
    #pragma unroll
    for (int i = 0; i < 8; ++i)
        #pragma unroll
        for (int j = 0; j < 4; ++j) acc[i][j] = 0ull;

    #pragma unroll 4
    for (int d = 0; d < DD; ++d) {
        float xs[8]; ull xp[8]; ull wp[4];
        #pragma unroll
        for (int i = 0; i < 8; ++i) xs[i] = xb[i*XS_PITCH + d];
        #pragma unroll
        for (int j = 0; j < 4; ++j) wp[j] = *(const ull*)(wb + d*WT_PITCH + 2*j);
        #pragma unroll
        for (int i = 0; i < 8; ++i) xp[i] = pack2(xs[i]);
        #pragma unroll
        for (int i = 0; i < 8; ++i)
            #pragma unroll
            for (int j = 0; j < 4; ++j) acc[i][j] = ffma2(xp[i], wp[j], acc[i][j]);
    }

    int rbase = rt*128 + tr*8;
    #pragma unroll
    for (int i = 0; i < 8; ++i) {
        float* orow = out + (rbase + i)*DD + tc*8;
        #pragma unroll
        for (int j = 0; j < 4; ++j) {
            float2 v = unpack2(acc[i][j]);
            float o0 = v.x + bs[tc*8 + 2*j+0];
            float o1 = v.y + bs[tc*8 + 2*j+1];
            if (mat != 2) { o0 = __expf(2.0f*o0); o1 = __expf(2.0f*o1); }
            orow[2*j+0] = o0;
            orow[2*j+1] = o1;
        }
    }
}

// =====================================================================
// Attention. Block = (batch b, 32-row q tile), 1024 threads (32 warps).
// Phase 1: tanh(q+k) = 1 - 2/(1+Eq*Ek).  Score (softmax-shifted):
//          s = -2 * sum_d w_d / (1 + Eq_d*Ek_d).
//          Warp = (q-pair, k-half); lane = (q_sub, k-pair (c,c+16)).
//          Per d-pair: D0,D1 via 1 ffma2 each; w0/D0+w1/D1 via
//          (w0*D1+w1*D0)*rcp(D0*D1) -> 2 MUFU per 4 elements.
// Phase 2: warp-per-row softmax.
// Phase 3: O = P @ V with fma.rn.f32x2 (k-adjacent V pairs).
// smem (floats):
//   S[32][512]                        @ 0      (16384)
//   EKs[128][33]ull / Vp[32][128]ull  @ 16384  (8448)
//   EQT[32][64]ull2 (Eq0dup,Eq1dup)   @ 24832  (8192)
//   WT[64]ull2 (w0dup,w1dup)          @ 33024  (256)
//   wall[128]                         @ 33280
//   rinv[32]                          @ 33408
// =====================================================================
#define SM_S    0
#define SM_EKS  (32*512)
#define SM_EQT  (SM_EKS + 8448)
#define SM_WT   (SM_EQT + 8192)
#define SM_WALL (SM_WT + 256)
#define SM_RINV (SM_WALL + 128)
#define ATTN_SMEM_FLOATS (SM_RINV + 32)   // 33440 floats = 133760 B

__global__ void __launch_bounds__(1024) attn_kernel(
    const float* __restrict__ wdel, const float* __restrict__ wsig,
    const float* __restrict__ wthe, float* __restrict__ out)
{
    extern __shared__ float sm[];
    float*      S    = sm + SM_S;
    ull*        EKs  = (ull*)(sm + SM_EKS);       // [128][33] pairs (c, c+16)
    ulonglong2* EQT  = (ulonglong2*)(sm + SM_EQT); // [32][64]
    ulonglong2* WT   = (ulonglong2*)(sm + SM_WT);  // [64]
    float*      wall = sm + SM_WALL;
    float*      rinv = sm + SM_RINV;

    int tid  = threadIdx.x;
    int w    = tid >> 5;
    int lane = tid & 31;
    int b    = blockIdx.x >> 4;
    int qt   = blockIdx.x & 15;
    int qbase = qt * 32;

    const float* EQg = g_EQ + (b*LL + qbase)*DD;
    const float* EKg = g_EK + b*LL*DD;
    const float* Vg  = g_V  + b*LL*DD;

    if (tid < DD) wall[tid] = INV_SCALE + wdel[tid] + wsig[tid] + wthe[tid];
    __syncthreads();

    // EQT[r][d2] = (dup(Eq[r][2d2]), dup(Eq[r][2d2+1]))
    #pragma unroll
    for (int it = 0; it < 2; ++it) {
        int e  = it*1024 + tid;            // 0..2047
        int r  = e >> 6, d2 = e & 63;
        float2 t2 = *(const float2*)(EQg + r*DD + 2*d2);
        ulonglong2 u; u.x = pack2(t2.x); u.y = pack2(t2.y);
        EQT[r*64 + d2] = u;
    }
    if (tid < 64) {
        ulonglong2 u;
        u.x = pack2(wall[2*tid]);
        u.y = pack2(wall[2*tid+1]);
        WT[tid] = u;
    }
    // first kt-loop __syncthreads orders EQT/WT for all warps

    // ---------------- Phase 1: scores ----------------
    int qp   = w & 15;          // q pair index
    int h    = w >> 4;          // k half (0: k<32, 1: k>=32)
    int qsub = lane >> 4;       // which q row of the pair
    int c    = lane & 15;       // k pair column
    int q    = 2*qp + qsub;
    int koff = h*16 + c;
    const ulonglong2* EQrow = EQT + q*64;
    const ull ONE2  = pack2(1.0f);
    const ull NEG22 = pack2(-2.0f);

    // staging map (c-fast within warp to avoid STS conflicts)
    int sh  = tid >> 9;         // 0..1
    int sd4 = (tid >> 4) & 31;  // 0..31
    int sc  = tid & 15;         // 0..15

    for (int kt = 0; kt < 8; ++kt) {
        __syncthreads();   // EKs region free
        {
            const float4* EK4 = (const float4*)(EKg + kt*64*DD);
            float4 a  = EK4[(sh*32+sc)*32 + sd4];
            float4 bb = EK4[(sh*32+sc+16)*32 + sd4];
            int kk = sh*16 + sc;
            EKs[(4*sd4+0)*33 + kk] = pack2two(a.x, bb.x);
            EKs[(4*sd4+1)*33 + kk] = pack2two(a.y, bb.y);
            EKs[(4*sd4+2)*33 + kk] = pack2two(a.z, bb.z);
            EKs[(4*sd4+3)*33 + kk] = pack2two(a.w, bb.w);
        }
        __syncthreads();

        ull acc = 0ull;
        #pragma unroll 4
        for (int d2 = 0; d2 < 64; ++d2) {
            ulonglong2 eq = EQrow[d2];
            ulonglong2 wp = WT[d2];
            ull K0 = EKs[(2*d2)*33 + koff];
            ull K1 = EKs[(2*d2+1)*33 + koff];
            ull D0 = ffma2(eq.x, K0, ONE2);            // 1 + Eq*Ek at d0
            ull D1 = ffma2(eq.y, K1, ONE2);
            ull num = ffma2(wp.y, D0, fmul2(wp.x, D1)); // w0*D1 + w1*D0
            ull Dp  = fmul2(D0, D1);
            float2 df = unpack2(Dp);
            ull R = pack2two(frcp(df.x), frcp(df.y));
            acc = ffma2(num, R, acc);
        }
        float2 s = unpack2(fmul2(acc, NEG22));
        S[q*512 + kt*64 + h*32 + c]      = s.x;
        S[q*512 + kt*64 + h*32 + c + 16] = s.y;
    }
    __syncthreads();   // row w assembled from 2 warps -> must sync

    // ---------------- Phase 2: softmax ----------------
    {
        float* Srow = S + w*512;
        float v[16];
        float m = -1e30f;
        #pragma unroll
        for (int i = 0; i < 16; ++i) { v[i] = Srow[i*32 + lane]; m = fmaxf(m, v[i]); }
        #pragma unroll
        for (int s = 16; s > 0; s >>= 1) m = fmaxf(m, __shfl_xor_sync(0xffffffffu, m, s));
        float sum = 0.f;
        #pragma unroll
        for (int i = 0; i < 16; ++i) {
            float e = __expf(v[i] - m);
            Srow[i*32 + lane] = e;
            sum += e;
        }
        #pragma unroll
        for (int s = 16; s > 0; s >>= 1) sum += __shfl_xor_sync(0xffffffffu, sum, s);
        if (lane == 0) rinv[w] = 1.0f / sum;
    }

    // ---------------- Phase 3: O = P @ V (FFMA2) ----------------
    int r0  = (w & 15) * 2;
    int dh  = w >> 4;
    int dA  = dh*64 + lane;
    ull acc3[2][2] = {{0,0},{0,0}};
    const ull* Vp = (const ull*)(sm + SM_EKS);   // [32][128] : Vp[k2][d]

    for (int kt = 0; kt < 8; ++kt) {
        __syncthreads();   // previous tile consumed (kt=0: phase-2 S/rinv done)
        {
            const float4* Va = (const float4*)(Vg + kt*64*DD);
            float2* Vp2 = (float2*)(sm + SM_EKS);
            int k2 = tid >> 5, d4 = tid & 31;
            float4 a  = Va[(2*k2)*32 + d4];
            float4 bb = Va[(2*k2+1)*32 + d4];
            Vp2[k2*128 + 4*d4 + 0] = make_float2(a.x, bb.x);
            Vp2[k2*128 + 4*d4 + 1] = make_float2(a.y, bb.y);
            Vp2[k2*128 + 4*d4 + 2] = make_float2(a.z, bb.z);
            Vp2[k2*128 + 4*d4 + 3] = make_float2(a.w, bb.w);
        }
        __syncthreads();

        const float* Sb = S + kt*64;
        #pragma unroll 4
        for (int k2 = 0; k2 < 32; ++k2) {
            ull p0 = *(const ull*)(Sb + (r0+0)*512 + 2*k2);
            ull p1 = *(const ull*)(Sb + (r0+1)*512 + 2*k2);
            ull v0 = Vp[k2*128 + dA];
            ull v1 = Vp[k2*128 + dA + 32];
            acc3[0][0] = ffma2(p0, v0, acc3[0][0]);  acc3[0][1] = ffma2(p0, v1, acc3[0][1]);
            acc3[1][0] = ffma2(p1, v0, acc3[1][0]);  acc3[1][1] = ffma2(p1, v1, acc3[1][1]);
        }
    }

    #pragma unroll
    for (int i = 0; i < 2; ++i) {
        float inv = rinv[r0 + i];
        float2 eo = unpack2(acc3[i][0]);
        float2 e1 = unpack2(acc3[i][1]);
        float* orow = out + (size_t)(b*LL + qbase + r0 + i)*DD;
        orow[dA]      = (eo.x + eo.y) * inv;
        orow[dA + 32] = (e1.x + e1.y) * inv;
    }
}

// =====================================================================
extern "C" void kernel_launch(void* const* d_in, const int* in_sizes, int n_in,
                              void* d_out, int out_size)
{
    const float* query = (const float*)d_in[0];
    const float* key   = (const float*)d_in[1];
    const float* value = (const float*)d_in[2];
    const float* Wq    = (const float*)d_in[3];
    const float* bq    = (const float*)d_in[4];
    const float* Wk    = (const float*)d_in[5];
    const float* bk    = (const float*)d_in[6];
    const float* Wv    = (const float*)d_in[7];
    const float* bv    = (const float*)d_in[8];
    const float* wdel  = (const float*)d_in[9];
    const float* wsig  = (const float*)d_in[11];
    const float* wthe  = (const float*)d_in[13];
    float* out = (float*)d_out;

    const int PROJ_SMEM = PROJ_SMEM_FLOATS * (int)sizeof(float);
    const int ATTN_SMEM = ATTN_SMEM_FLOATS * (int)sizeof(float);

    cudaFuncSetAttribute(proj_kernel, cudaFuncAttributeMaxDynamicSharedMemorySize, PROJ_SMEM);
    cudaFuncSetAttribute(attn_kernel, cudaFuncAttributeMaxDynamicSharedMemorySize, ATTN_SMEM);

    proj_kernel<<<96, 256, PROJ_SMEM>>>(query, key, value, Wq, bq, Wk, bk, Wv, bv);
    attn_kernel<<<BB*16, 1024, ATTN_SMEM>>>(wdel, wsig, wthe, out);
}

// round 11
// speedup vs baseline: 1.2118x; 1.1799x over previous
#include <cuda_runtime.h>

#define BB 8
#define LL 512
#define DD 128
#define INV_SCALE 0.08838834764831843f   // 1/sqrt(128)

typedef unsigned long long ull;

// ---- scratch (no cudaMalloc allowed) ----
__device__ float g_EQ[BB*LL*DD];   // exp(2*Qproj)
__device__ float g_EK[BB*LL*DD];   // exp(2*Kproj)
__device__ float g_V [BB*LL*DD];

__device__ __forceinline__ float frcp(float x) {
    float y;
    asm("rcp.approx.f32 %0, %1;" : "=f"(y) : "f"(x));
    return y;
}
__device__ __forceinline__ ull ffma2(ull a, ull b, ull c) {
    ull d;
    asm("fma.rn.f32x2 %0, %1, %2, %3;" : "=l"(d) : "l"(a), "l"(b), "l"(c));
    return d;
}
__device__ __forceinline__ ull fmul2(ull a, ull b) {
    ull d;
    asm("mul.rn.f32x2 %0, %1, %2;" : "=l"(d) : "l"(a), "l"(b));
    return d;
}
__device__ __forceinline__ ull pack2(float x) {
    ull d;
    asm("mov.b64 %0, {%1, %1};" : "=l"(d) : "f"(x));
    return d;
}
__device__ __forceinline__ ull pack2two(float x, float y) {
    ull d;
    asm("mov.b64 %0, {%1, %2};" : "=l"(d) : "f"(x), "f"(y));
    return d;
}
__device__ __forceinline__ float2 unpack2(ull v) {
    float2 r;
    asm("mov.b64 {%0, %1}, %2;" : "=f"(r.x), "=f"(r.y) : "l"(v));
    return r;
}

// =====================================================================
// Projection: FFMA2 GEMM, 64-row tiles -> grid 192 (full chip, 2 CTA/SM)
// epilogue writes exp(2*(XW^T+b)) for Q,K and raw proj for V.
// smem: Xs[64][129] + Wt[128][130] = 99584 B
// =====================================================================
#define XS_PITCH 129
#define WT_PITCH 130
#define PROJ_SMEM_FLOATS (64*XS_PITCH + 128*WT_PITCH)

__global__ void __launch_bounds__(256) proj_kernel(
    const float* __restrict__ Xq, const float* __restrict__ Xk, const float* __restrict__ Xv,
    const float* __restrict__ Wq, const float* __restrict__ bq,
    const float* __restrict__ Wk, const float* __restrict__ bk,
    const float* __restrict__ Wv, const float* __restrict__ bv)
{
    extern __shared__ float sm[];
    float* Xs = sm;                    // [64][129]
    float* Wt = sm + 64*XS_PITCH;      // [128][130]  Wt[d][c]
    __shared__ float bs[DD];

    int bx  = blockIdx.x;
    int mat = bx >> 6;
    int rt  = bx & 63;
    const float *X, *W, *bias;
    float* out;
    if (mat == 0)      { X = Xq; W = Wq; bias = bq; out = g_EQ; }
    else if (mat == 1) { X = Xk; W = Wk; bias = bk; out = g_EK; }
    else               { X = Xv; W = Wv; bias = bv; out = g_V;  }

    int tid = threadIdx.x;
    const float4* Xg = (const float4*)(X + rt*64*DD);
    const float4* Wg = (const float4*)W;
    #pragma unroll
    for (int it = 0; it < 8; ++it) {           // X tile: 64 rows
        int idx = it*256 + tid;                // 0..2047 float4 groups
        int d4  = idx & 31;
        int r   = idx >> 5;
        float4 xv = Xg[idx];
        float* xd = Xs + r*XS_PITCH + 4*d4;
        xd[0] = xv.x; xd[1] = xv.y; xd[2] = xv.z; xd[3] = xv.w;
    }
    #pragma unroll
    for (int it = 0; it < 16; ++it) {          // W: 128x128
        int idx = it*256 + tid;                // 0..4095
        int d4  = idx & 31;
        int r   = idx >> 5;
        float4 wv = Wg[idx];
        Wt[(4*d4+0)*WT_PITCH + r] = wv.x;
        Wt[(4*d4+1)*WT_PITCH + r] = wv.y;
        Wt[(4*d4+2)*WT_PITCH + r] = wv.z;
        Wt[(4*d4+3)*WT_PITCH + r] = wv.w;
    }
    if (tid < DD) bs[tid] = bias[tid];
    __syncthreads();

    int tr = tid >> 4;     // 0..15 (4-row group)
    int tc = tid & 15;     // 0..15 (8-col group)
    const float* xb = Xs + (tr*4)*XS_PITCH;
    const float* wb = Wt + tc*8;

    ull acc[4][4];
    #pragma unroll
    for (int i = 0; i < 4; ++i)
        #pragma unroll
        for (int j = 0; j < 4; ++j) acc[i][j] = 0ull;

    #pragma unroll 4
    for (int d = 0; d < DD; ++d) {
        float xs[4]; ull xp[4]; ull wp[4];
        #pragma unroll
        for (int i = 0; i < 4; ++i) xs[i] = xb[i*XS_PITCH + d];
        #pragma unroll
        for (int j = 0; j < 4; ++j) wp[j] = *(const ull*)(wb + d*WT_PITCH + 2*j);
        #pragma unroll
        for (int i = 0; i < 4; ++i) xp[i] = pack2(xs[i]);
        #pragma unroll
        for (int i = 0; i < 4; ++i)
            #pragma unroll
            for (int j = 0; j < 4; ++j) acc[i][j] = ffma2(xp[i], wp[j], acc[i][j]);
    }

    int rbase = rt*64 + tr*4;
    #pragma unroll
    for (int i = 0; i < 4; ++i) {
        float* orow = out + (rbase + i)*DD + tc*8;
        #pragma unroll
        for (int j = 0; j < 4; ++j) {
            float2 v = unpack2(acc[i][j]);
            float o0 = v.x + bs[tc*8 + 2*j+0];
            float o1 = v.y + bs[tc*8 + 2*j+1];
            if (mat != 2) { o0 = __expf(2.0f*o0); o1 = __expf(2.0f*o1); }
            orow[2*j+0] = o0;
            orow[2*j+1] = o1;
        }
    }
}

// =====================================================================
// Attention. Block = (batch b, 32-q tile), 1024 threads (32 warps).
// Phase 1 (lane=q, f32x2 over adjacent-k pairs, pair-4 rcp over d):
//   score(softmax-shifted) = -2 * sum_d w_d / (1 + Eq_d*Ek_d)
//   Per d4, per k-pair j:  D_i = ffma2(dup(Eq_i), ekpair_i, 1)
//   sum w_i/D_i over 4 d's via one f32x2-pair of rcp:
//     N = n01*P23 + n23*P01,  n01 = w0*D1+w1*D0,  P01=D0*D1, ...
//   Warp w owns k-slice [4w, 4w+4) of each 128-k tile (4 tiles).
// Phase 2: warp-per-row softmax.
// Phase 3: O = P @ V with fma.rn.f32x2 (R8 scheme, S pitch 516).
// smem (floats):
//   S[32][516]          @ 0       16512
//   EKa[32][65] ull2    @ 16512    8320   (pairs d0,d1; Vp reuses this)
//   EKb[32][65] ull2    @ 24832    8320   (pairs d2,d3)
//   EQ4[32][32] float4  @ 33152    4096   (EQ4[d4][q] non-dup)
//   WTa[32] ull2        @ 37248     128   (dup w0, dup w1)
//   WTb[32] ull2        @ 37376     128
//   rinv[32]            @ 37504
// =====================================================================
#define S_PITCH 516
#define SM_S    0
#define SM_EKA  16512
#define SM_EKB  24832
#define SM_EQ4  33152
#define SM_WTA  37248
#define SM_WTB  37376
#define SM_RINV 37504
#define ATTN_SMEM_FLOATS 37536    // 150144 B

__global__ void __launch_bounds__(1024) attn_kernel(
    const float* __restrict__ wdel, const float* __restrict__ wsig,
    const float* __restrict__ wthe, float* __restrict__ out)
{
    extern __shared__ float sm[];
    float*      S    = sm + SM_S;
    ulonglong2* EKa  = (ulonglong2*)(sm + SM_EKA);   // [32][65]
    ulonglong2* EKb  = (ulonglong2*)(sm + SM_EKB);   // [32][65]
    float4*     EQ4  = (float4*)(sm + SM_EQ4);       // [d4][q]
    ulonglong2* WTa  = (ulonglong2*)(sm + SM_WTA);
    ulonglong2* WTb  = (ulonglong2*)(sm + SM_WTB);
    float*      rinv = sm + SM_RINV;

    int tid  = threadIdx.x;
    int w    = tid >> 5;
    int lane = tid & 31;
    int b    = blockIdx.x >> 4;
    int qt   = blockIdx.x & 15;
    int qbase = qt * 32;

    const float* EQg = g_EQ + (b*LL + qbase)*DD;
    const float* EKg = g_EK + b*LL*DD;
    const float* Vg  = g_V  + b*LL*DD;

    // ---- init tables ----
    if (tid < 32) {
        float w0 = INV_SCALE + wdel[4*tid+0] + wsig[4*tid+0] + wthe[4*tid+0];
        float w1 = INV_SCALE + wdel[4*tid+1] + wsig[4*tid+1] + wthe[4*tid+1];
        float w2 = INV_SCALE + wdel[4*tid+2] + wsig[4*tid+2] + wthe[4*tid+2];
        float w3 = INV_SCALE + wdel[4*tid+3] + wsig[4*tid+3] + wthe[4*tid+3];
        ulonglong2 ua; ua.x = pack2(w0); ua.y = pack2(w1); WTa[tid] = ua;
        ulonglong2 ub; ub.x = pack2(w2); ub.y = pack2(w3); WTb[tid] = ub;
    }
    {   // EQ4[d4][q] = float4 of Eq[q][4d4..4d4+3]
        int q  = tid & 31;
        int d4 = tid >> 5;
        EQ4[d4*32 + q] = ((const float4*)EQg)[q*32 + d4];
    }
    // ordered by first kt-loop __syncthreads

    // ---------------- Phase 1: scores ----------------
    const ull ONE2  = pack2(1.0f);
    const ull NEG22 = pack2(-2.0f);
    int j0 = 2*w;                 // this warp's k-pair indices (j0, j0+1)

    for (int kt = 0; kt < 4; ++kt) {          // 4 tiles of 128 k
        __syncthreads();   // EK region free (covers table init on kt=0)
        {   // stage 128-k tile: cells (d4, j), j = k-pair 0..63
            const float4* EK4g = (const float4*)(EKg + kt*128*DD);
            #pragma unroll
            for (int it = 0; it < 2; ++it) {
                int cidx = it*1024 + tid;      // 0..2047
                int d4 = cidx & 31;
                int j  = cidx >> 5;            // 0..63
                float4 a  = EK4g[(2*j)*32 + d4];
                float4 bb = EK4g[(2*j+1)*32 + d4];
                ulonglong2 ua; ua.x = pack2two(a.x, bb.x); ua.y = pack2two(a.y, bb.y);
                ulonglong2 ub; ub.x = pack2two(a.z, bb.z); ub.y = pack2two(a.w, bb.w);
                EKa[d4*65 + j] = ua;
                EKb[d4*65 + j] = ub;
            }
        }
        __syncthreads();

        ull acc0 = 0ull, acc1 = 0ull;
        #pragma unroll 4
        for (int d4 = 0; d4 < 32; ++d4) {
            float4 eqv = EQ4[d4*32 + lane];
            ull eq0 = pack2(eqv.x), eq1 = pack2(eqv.y);
            ull eq2 = pack2(eqv.z), eq3 = pack2(eqv.w);
            ulonglong2 wa = WTa[d4];
            ulonglong2 wb = WTb[d4];
            #pragma unroll
            for (int jj = 0; jj < 2; ++jj) {
                ulonglong2 ka = EKa[d4*65 + j0 + jj];
                ulonglong2 kb = EKb[d4*65 + j0 + jj];
                ull D0 = ffma2(eq0, ka.x, ONE2);
                ull D1 = ffma2(eq1, ka.y, ONE2);
                ull D2 = ffma2(eq2, kb.x, ONE2);
                ull D3 = ffma2(eq3, kb.y, ONE2);
                ull P01 = fmul2(D0, D1);
                ull P23 = fmul2(D2, D3);
                ull n01 = ffma2(wa.y, D0, fmul2(wa.x, D1));
                ull n23 = ffma2(wb.y, D2, fmul2(wb.x, D3));
                ull N   = ffma2(n23, P01, fmul2(n01, P23));
                ull Dp  = fmul2(P01, P23);
                float2 df = unpack2(Dp);
                ull R = pack2two(frcp(df.x), frcp(df.y));
                if (jj == 0) acc0 = ffma2(N, R, acc0);
                else         acc1 = ffma2(N, R, acc1);
            }
        }
        float2 s0 = unpack2(fmul2(acc0, NEG22));
        float2 s1 = unpack2(fmul2(acc1, NEG22));
        *(float4*)(S + lane*S_PITCH + kt*128 + 4*w) = make_float4(s0.x, s0.y, s1.x, s1.y);
    }
    __syncthreads();   // each row assembled from all 32 warps

    // ---------------- Phase 2: softmax ----------------
    {
        float* Srow = S + w*S_PITCH;
        float v[16];
        float m = -1e30f;
        #pragma unroll
        for (int i = 0; i < 16; ++i) { v[i] = Srow[i*32 + lane]; m = fmaxf(m, v[i]); }
        #pragma unroll
        for (int s = 16; s > 0; s >>= 1) m = fmaxf(m, __shfl_xor_sync(0xffffffffu, m, s));
        float sum = 0.f;
        #pragma unroll
        for (int i = 0; i < 16; ++i) {
            float e = __expf(v[i] - m);
            Srow[i*32 + lane] = e;
            sum += e;
        }
        #pragma unroll
        for (int s = 16; s > 0; s >>= 1) sum += __shfl_xor_sync(0xffffffffu, sum, s);
        if (lane == 0) rinv[w] = 1.0f / sum;
    }

    // ---------------- Phase 3: O = P @ V (FFMA2) ----------------
    int r0  = (w & 15) * 2;
    int dh  = w >> 4;
    int dA  = dh*64 + lane;
    ull acc3[2][2] = {{0,0},{0,0}};
    const ull* Vp = (const ull*)(sm + SM_EKA);   // [32][128] : Vp[k2][d]

    for (int kt = 0; kt < 8; ++kt) {             // 8 tiles of 64 k
        __syncthreads();   // previous tile consumed (kt=0: softmax done)
        {
            const float4* Va = (const float4*)(Vg + kt*64*DD);
            float2* Vp2 = (float2*)(sm + SM_EKA);
            int k2 = tid >> 5, d4 = tid & 31;
            float4 a  = Va[(2*k2)*32 + d4];
            float4 bb = Va[(2*k2+1)*32 + d4];
            Vp2[k2*128 + 4*d4 + 0] = make_float2(a.x, bb.x);
            Vp2[k2*128 + 4*d4 + 1] = make_float2(a.y, bb.y);
            Vp2[k2*128 + 4*d4 + 2] = make_float2(a.z, bb.z);
            Vp2[k2*128 + 4*d4 + 3] = make_float2(a.w, bb.w);
        }
        __syncthreads();

        const float* Sb = S + kt*64;
        #pragma unroll 4
        for (int k2 = 0; k2 < 32; ++k2) {
            ull p0 = *(const ull*)(Sb + (r0+0)*S_PITCH + 2*k2);
            ull p1 = *(const ull*)(Sb + (r0+1)*S_PITCH + 2*k2);
            ull v0 = Vp[k2*128 + dA];
            ull v1 = Vp[k2*128 + dA + 32];
            acc3[0][0] = ffma2(p0, v0, acc3[0][0]);  acc3[0][1] = ffma2(p0, v1, acc3[0][1]);
            acc3[1][0] = ffma2(p1, v0, acc3[1][0]);  acc3[1][1] = ffma2(p1, v1, acc3[1][1]);
        }
    }

    #pragma unroll
    for (int i = 0; i < 2; ++i) {
        float inv = rinv[r0 + i];
        float2 eo = unpack2(acc3[i][0]);
        float2 e1 = unpack2(acc3[i][1]);
        float* orow = out + (size_t)(b*LL + qbase + r0 + i)*DD;
        orow[dA]      = (eo.x + eo.y) * inv;
        orow[dA + 32] = (e1.x + e1.y) * inv;
    }
}

// =====================================================================
extern "C" void kernel_launch(void* const* d_in, const int* in_sizes, int n_in,
                              void* d_out, int out_size)
{
    const float* query = (const float*)d_in[0];
    const float* key   = (const float*)d_in[1];
    const float* value = (const float*)d_in[2];
    const float* Wq    = (const float*)d_in[3];
    const float* bq    = (const float*)d_in[4];
    const float* Wk    = (const float*)d_in[5];
    const float* bk    = (const float*)d_in[6];
    const float* Wv    = (const float*)d_in[7];
    const float* bv    = (const float*)d_in[8];
    const float* wdel  = (const float*)d_in[9];
    const float* wsig  = (const float*)d_in[11];
    const float* wthe  = (const float*)d_in[13];
    float* out = (float*)d_out;

    const int PROJ_SMEM = PROJ_SMEM_FLOATS * (int)sizeof(float);
    const int ATTN_SMEM = ATTN_SMEM_FLOATS * (int)sizeof(float);

    cudaFuncSetAttribute(proj_kernel, cudaFuncAttributeMaxDynamicSharedMemorySize, PROJ_SMEM);
    cudaFuncSetAttribute(attn_kernel, cudaFuncAttributeMaxDynamicSharedMemorySize, ATTN_SMEM);

    proj_kernel<<<192, 256, PROJ_SMEM>>>(query, key, value, Wq, bq, Wk, bk, Wv, bv);
    attn_kernel<<<BB*16, 1024, ATTN_SMEM>>>(wdel, wsig, wthe, out);
}